// round 1
// baseline (speedup 1.0000x reference)
#include <cuda_runtime.h>
#include <cstdint>

#define TB   512
#define TM1  127
#define ENCD 256
#define GBATCH 4
#define NCTA (TB / GBATCH)   // 128

// ---------------- scratch (static device globals; no runtime allocation) ----
static __device__ float  g_E[TB * TM1 * ENCD];       // E[b,t,k] = W_e@enc + b_attn1  (~63.5 MiB)
static __device__ float4 g_W1v[128 * 256];           // [jb][k]: W_attn1[k][4jb..4jb+3] (hc part, j<512)
static __device__ float  g_W1eT[256 * 256];          // [j][k]:  W_attn1[k][512+j]
static __device__ float4 g_Whh4[256 * 256];          // [j][k]:  gates (i,f,g,o) weights W_hh[k+256q][j]
static __device__ float4 g_bih4[256];                // per k: b_ih+b_hh for gates i,f,g,o
static __device__ float4 g_wih4[256];                // per k: W_ih for gates i,f,g,o

// ---------------- math helpers ---------------------------------------------
__device__ __forceinline__ float tanh_fast(float x) {
    float y; asm("tanh.approx.f32 %0, %1;" : "=f"(y) : "f"(x)); return y;
}
__device__ __forceinline__ float sigm(float x) { return 1.f / (1.f + __expf(-x)); }
__device__ __forceinline__ float tanh_acc(float x) {
    float e = __expf(2.f * x); return 1.f - 2.f / (e + 1.f);
}

// valid result only on thread 0
__device__ __forceinline__ float blockReduceSum(float v) {
    __shared__ float sred[8];
    const int lane = threadIdx.x & 31, wid = threadIdx.x >> 5;
    #pragma unroll
    for (int o = 16; o; o >>= 1) v += __shfl_down_sync(0xffffffffu, v, o);
    if (lane == 0) sred[wid] = v;
    __syncthreads();
    float r = (wid == 0 && lane < 8) ? sred[lane] : 0.f;
    if (wid == 0) {
        #pragma unroll
        for (int o = 16; o; o >>= 1) r += __shfl_down_sync(0xffffffffu, r, o);
    }
    __syncthreads();   // protect sred for the next call
    return r;
}

// ---------------- prep: transposes / packing --------------------------------
__global__ void prep_kernel(const float* __restrict__ W1, const float* __restrict__ Whh,
                            const float* __restrict__ bih, const float* __restrict__ bhh,
                            const float* __restrict__ Wih) {
    const int tid = blockIdx.x * blockDim.x + threadIdx.x;
    const int stride = gridDim.x * blockDim.x;
    for (int i = tid; i < 128 * 256; i += stride) {
        int jb = i >> 8, k = i & 255;
        const float* p = W1 + k * 768 + jb * 4;
        g_W1v[i] = make_float4(p[0], p[1], p[2], p[3]);
    }
    for (int i = tid; i < 256 * 256; i += stride) {
        int j = i >> 8, k = i & 255;
        g_W1eT[i] = W1[k * 768 + 512 + j];
    }
    for (int i = tid; i < 256 * 256; i += stride) {
        int j = i >> 8, k = i & 255;
        g_Whh4[i] = make_float4(Whh[k * 256 + j], Whh[(k + 256) * 256 + j],
                                Whh[(k + 512) * 256 + j], Whh[(k + 768) * 256 + j]);
    }
    for (int i = tid; i < 256; i += stride) {
        g_bih4[i] = make_float4(bih[i] + bhh[i], bih[i + 256] + bhh[i + 256],
                                bih[i + 512] + bhh[i + 512], bih[i + 768] + bhh[i + 768]);
        g_wih4[i] = make_float4(Wih[i], Wih[i + 256], Wih[i + 512], Wih[i + 768]);
    }
}

// ---------------- E = enc @ W_e^T + b_attn1 : [65024,256] x [256,256] -------
__global__ __launch_bounds__(256) void e_gemm(const float* __restrict__ A,
                                              const float* __restrict__ bias) {
    __shared__ float As[16][64];
    __shared__ float Bs[16][64];
    const int tid = threadIdx.x;
    const int row0 = blockIdx.x * 64;
    const int col0 = blockIdx.y * 64;
    const int tx = tid & 15, ty = tid >> 4;
    float acc[4][4] = {};
    for (int k0 = 0; k0 < 256; k0 += 16) {
        #pragma unroll
        for (int i = tid; i < 1024; i += 256) {
            int m = i >> 4, kk = i & 15;
            As[kk][m] = A[(size_t)(row0 + m) * 256 + k0 + kk];
        }
        {
            int kk = tid >> 4, n4 = tid & 15;
            ((float4*)&Bs[kk][0])[n4] =
                ((const float4*)&g_W1eT[(k0 + kk) * 256 + col0])[n4];
        }
        __syncthreads();
        #pragma unroll
        for (int kk = 0; kk < 16; kk++) {
            float4 av = ((const float4*)&As[kk][0])[ty];
            float4 bv = ((const float4*)&Bs[kk][0])[tx];
            acc[0][0] += av.x * bv.x; acc[0][1] += av.x * bv.y; acc[0][2] += av.x * bv.z; acc[0][3] += av.x * bv.w;
            acc[1][0] += av.y * bv.x; acc[1][1] += av.y * bv.y; acc[1][2] += av.y * bv.z; acc[1][3] += av.y * bv.w;
            acc[2][0] += av.z * bv.x; acc[2][1] += av.z * bv.y; acc[2][2] += av.z * bv.z; acc[2][3] += av.z * bv.w;
            acc[3][0] += av.w * bv.x; acc[3][1] += av.w * bv.y; acc[3][2] += av.w * bv.z; acc[3][3] += av.w * bv.w;
        }
        __syncthreads();
    }
    float4 bv = ((const float4*)(bias + col0))[tx];
    #pragma unroll
    for (int i = 0; i < 4; i++) {
        int row = row0 + ty * 4 + i;
        float4 o = make_float4(acc[i][0] + bv.x, acc[i][1] + bv.y,
                               acc[i][2] + bv.z, acc[i][3] + bv.w);
        ((float4*)&g_E[(size_t)row * 256 + col0])[tx] = o;
    }
}

// ---------------- persistent decoder: 1 CTA = 4 batch rows, 127 steps -------
__global__ __launch_bounds__(256, 1) void decoder_kernel(
    const float* __restrict__ enc, const float* __restrict__ yhist,
    const float* __restrict__ w2,
    const float* __restrict__ Wfc, const float* __restrict__ bfc,
    const float* __restrict__ Wfcf, const float* __restrict__ bfcf,
    float* __restrict__ out) {
    __shared__ float shc[GBATCH][512];     // [g][0:256]=h, [256:512]=c
    __shared__ float sphc[GBATCH][256];
    __shared__ float sctx[GBATCH][256];
    __shared__ float sattn[GBATCH][128];
    __shared__ float w2s[256];
    __shared__ float wfcs[256];
    __shared__ float sy[GBATCH];

    const int tid = threadIdx.x;
    const int lane = tid & 31, warp = tid >> 5;
    const int bs = blockIdx.x * GBATCH;

    w2s[tid] = w2[tid];
    wfcs[tid] = Wfc[tid];
    #pragma unroll
    for (int g = 0; g < GBATCH; g++) { shc[g][tid] = 0.f; shc[g][256 + tid] = 0.f; }
    const float wfc_y = Wfc[256];
    const float bfc_v = bfc[0];
    __syncthreads();

    for (int step = 0; step < TM1; step++) {
        // -------- Phase A: phc[g][k] = W1_hc[k,:] . [h;c] --------------------
        {
            float a[GBATCH];
            #pragma unroll
            for (int g = 0; g < GBATCH; g++) a[g] = 0.f;
            #pragma unroll 4
            for (int jb = 0; jb < 128; jb++) {
                float4 w = g_W1v[(jb << 8) + tid];
                #pragma unroll
                for (int g = 0; g < GBATCH; g++) {
                    float4 x = ((const float4*)shc[g])[jb];
                    a[g] += w.x * x.x + w.y * x.y + w.z * x.z + w.w * x.w;
                }
            }
            #pragma unroll
            for (int g = 0; g < GBATCH; g++) sphc[g][tid] = a[g];
        }
        __syncthreads();
        // -------- Phase B: scores[g][t] = sum_k w2_k tanh(phc + E) -----------
        {
            for (int t = warp; t < TM1; t += 8) {
                const float4* Ev = (const float4*)g_E + ((size_t)bs * TM1 + t) * 64;
                float s[GBATCH];
                #pragma unroll
                for (int g = 0; g < GBATCH; g++) s[g] = 0.f;
                #pragma unroll
                for (int it = 0; it < 2; it++) {
                    int q = lane + (it << 5);
                    float4 wv = ((const float4*)w2s)[q];
                    #pragma unroll
                    for (int g = 0; g < GBATCH; g++) {
                        float4 p = ((const float4*)sphc[g])[q];
                        float4 e = Ev[g * (TM1 * 64) + q];
                        s[g] += wv.x * tanh_fast(p.x + e.x) + wv.y * tanh_fast(p.y + e.y)
                              + wv.z * tanh_fast(p.z + e.z) + wv.w * tanh_fast(p.w + e.w);
                    }
                }
                #pragma unroll
                for (int o = 16; o; o >>= 1) {
                    #pragma unroll
                    for (int g = 0; g < GBATCH; g++)
                        s[g] += __shfl_xor_sync(0xffffffffu, s[g], o);
                }
                if (lane == 0) {
                    #pragma unroll
                    for (int g = 0; g < GBATCH; g++) sattn[g][t] = s[g];
                }
            }
        }
        __syncthreads();
        // -------- Phase C1: softmax over t + write attention output ----------
        if (warp < GBATCH) {
            const int g = warp;
            float m = -1e30f;
            for (int t = lane; t < TM1; t += 32) m = fmaxf(m, sattn[g][t]);
            #pragma unroll
            for (int o = 16; o; o >>= 1) m = fmaxf(m, __shfl_xor_sync(0xffffffffu, m, o));
            float sum = 0.f;
            for (int t = lane; t < TM1; t += 32) {
                float e = __expf(sattn[g][t] - m); sattn[g][t] = e; sum += e;
            }
            #pragma unroll
            for (int o = 16; o; o >>= 1) sum += __shfl_xor_sync(0xffffffffu, sum, o);
            const float inv = 1.f / sum;
            float* wrow = out + TB + ((size_t)(bs + g) * TM1 + step) * TM1;
            for (int t = lane; t < TM1; t += 32) {
                float a = sattn[g][t] * inv; sattn[g][t] = a; wrow[t] = a;
            }
        }
        __syncthreads();
        // -------- Phase C2: context[g][e] = sum_t attn * enc -----------------
        {
            const int g = tid >> 6, q = tid & 63;
            const float4* ev = (const float4*)enc + ((size_t)(bs + g) * TM1) * 64 + q;
            float4 acc = make_float4(0.f, 0.f, 0.f, 0.f);
            #pragma unroll 4
            for (int t = 0; t < TM1; t++) {
                float a = sattn[g][t];
                float4 v = ev[(size_t)t * 64];
                acc.x += a * v.x; acc.y += a * v.y; acc.z += a * v.z; acc.w += a * v.w;
            }
            ((float4*)sctx[g])[q] = acc;
        }
        __syncthreads();
        // -------- y_tilde per g ----------------------------------------------
        #pragma unroll
        for (int g = 0; g < GBATCH; g++) {
            float tot = blockReduceSum(wfcs[tid] * sctx[g][tid]);
            if (tid == 0)
                sy[g] = bfc_v + wfc_y * yhist[(bs + g) * TM1 + step] + tot;
        }
        __syncthreads();
        // -------- Phase D: LSTM gates + state update -------------------------
        {
            const float4 b4 = g_bih4[tid], wi4 = g_wih4[tid];
            float4 acc[GBATCH];
            #pragma unroll
            for (int g = 0; g < GBATCH; g++) {
                float y = sy[g];
                acc[g] = make_float4(b4.x + wi4.x * y, b4.y + wi4.y * y,
                                     b4.z + wi4.z * y, b4.w + wi4.w * y);
            }
            #pragma unroll 4
            for (int j = 0; j < 256; j++) {
                float4 w = g_Whh4[(j << 8) + tid];
                #pragma unroll
                for (int g = 0; g < GBATCH; g++) {
                    float h = shc[g][j];
                    acc[g].x += w.x * h; acc[g].y += w.y * h;
                    acc[g].z += w.z * h; acc[g].w += w.w * h;
                }
            }
            __syncthreads();   // all reads of h done before overwriting
            #pragma unroll
            for (int g = 0; g < GBATCH; g++) {
                float cold = shc[g][256 + tid];
                float cn = sigm(acc[g].y) * cold + sigm(acc[g].x) * tanh_acc(acc[g].z);
                shc[g][256 + tid] = cn;
                shc[g][tid] = sigm(acc[g].w) * tanh_acc(cn);
            }
        }
        __syncthreads();
    }
    // -------- final: out[b] = b_fcf + Wfcf . [h ; context] -------------------
    #pragma unroll
    for (int g = 0; g < GBATCH; g++) {
        float tot = blockReduceSum(Wfcf[tid] * shc[g][tid] + Wfcf[256 + tid] * sctx[g][tid]);
        if (tid == 0) out[bs + g] = bfcf[0] + tot;
    }
}

// ---------------- launch -----------------------------------------------------
extern "C" void kernel_launch(void* const* d_in, const int* in_sizes, int n_in,
                              void* d_out, int out_size) {
    const float* enc  = (const float*)d_in[0];
    const float* yh   = (const float*)d_in[1];
    const float* W1   = (const float*)d_in[2];
    const float* b1   = (const float*)d_in[3];
    const float* W2   = (const float*)d_in[4];
    // d_in[5] = b_attn2: softmax-invariant, unused
    const float* Wih  = (const float*)d_in[6];
    const float* Whh  = (const float*)d_in[7];
    const float* bih  = (const float*)d_in[8];
    const float* bhh  = (const float*)d_in[9];
    const float* Wfc  = (const float*)d_in[10];
    const float* bfc  = (const float*)d_in[11];
    const float* Wfcf = (const float*)d_in[12];
    const float* bfcf = (const float*)d_in[13];
    float* out = (float*)d_out;

    prep_kernel<<<64, 256>>>(W1, Whh, bih, bhh, Wih);
    e_gemm<<<dim3(1016, 4), 256>>>(enc, b1);
    decoder_kernel<<<NCTA, 256>>>(enc, yh, W2, Wfc, bfc, Wfcf, bfcf, out);
}

// round 2
// speedup vs baseline: 2.9611x; 2.9611x over previous
#include <cuda_runtime.h>
#include <cuda_fp16.h>
#include <cstdint>

#define TB   512
#define TM1  127
#define ENCD 256
#define GB   4
#define NCTA (TB / GB)   // 128

// ---------------- scratch (static device globals) ---------------------------
static __device__ __half g_EH[TB * TM1 * ENCD];    // E[b,t,k] fp16  (~33 MB)
static __device__ __half g_encH[TB * TM1 * ENCD];  // enc fp16       (~33 MB)
static __device__ uint2  g_W1h[128 * 256];         // (jb,k): 4 fp16 of W1hc[k][4jb..]
static __device__ uint4  g_WhhH[128 * 256];        // (j2,k): gates(i,f | g,o) fp16 for j0,j1
static __device__ float  g_W1eT[256 * 256];        // [j][k]: W_attn1[k][512+j]
static __device__ float4 g_bih4[256];              // b_ih+b_hh per gate
static __device__ float4 g_wih4[256];              // W_ih per gate

// ---------------- math helpers ----------------------------------------------
__device__ __forceinline__ float tanh_fast(float x) {
    float y; asm("tanh.approx.f32 %0, %1;" : "=f"(y) : "f"(x)); return y;
}
__device__ __forceinline__ float sigm(float x) { return 1.f / (1.f + __expf(-x)); }
__device__ __forceinline__ float tanh_acc(float x) {
    float e = __expf(2.f * x); return 1.f - 2.f / (e + 1.f);
}
__device__ __forceinline__ unsigned long long pk2(float x, float y) {
    unsigned long long r; asm("mov.b64 %0, {%1,%2};" : "=l"(r) : "f"(x), "f"(y)); return r;
}
__device__ __forceinline__ void fma2(unsigned long long& d, unsigned long long a,
                                     unsigned long long b) {
    asm("fma.rn.f32x2 %0, %1, %2, %0;" : "+l"(d) : "l"(a), "l"(b));
}
__device__ __forceinline__ float2 up2(unsigned long long v) {
    float2 f; asm("mov.b64 {%0,%1}, %2;" : "=f"(f.x), "=f"(f.y) : "l"(v)); return f;
}
__device__ __forceinline__ float2 h2f(unsigned u) {
    return __half22float2(*(__half2*)&u);
}

// block reduce over 512 threads; valid on thread 0 only
__device__ __forceinline__ float blockReduceSum(float v) {
    __shared__ float sred[16];
    const int lane = threadIdx.x & 31, wid = threadIdx.x >> 5;
    #pragma unroll
    for (int o = 16; o; o >>= 1) v += __shfl_down_sync(0xffffffffu, v, o);
    if (lane == 0) sred[wid] = v;
    __syncthreads();
    float r = 0.f;
    if (wid == 0) {
        r = (lane < 16) ? sred[lane] : 0.f;
        #pragma unroll
        for (int o = 8; o; o >>= 1) r += __shfl_down_sync(0xffffffffu, r, o);
    }
    __syncthreads();
    return r;
}

// ---------------- prep: packing / fp16 conversion ---------------------------
__global__ void prep_kernel(const float* __restrict__ W1, const float* __restrict__ Whh,
                            const float* __restrict__ bih, const float* __restrict__ bhh,
                            const float* __restrict__ Wih, const float* __restrict__ enc) {
    const int tid = blockIdx.x * blockDim.x + threadIdx.x;
    const int stride = gridDim.x * blockDim.x;
    for (int i = tid; i < 128 * 256; i += stride) {
        int jb = i >> 8, k = i & 255;
        const float* p = W1 + k * 768 + jb * 4;
        __half2 a = __floats2half2_rn(p[0], p[1]);
        __half2 b = __floats2half2_rn(p[2], p[3]);
        uint2 u; u.x = *(unsigned*)&a; u.y = *(unsigned*)&b;
        g_W1h[i] = u;
    }
    for (int i = tid; i < 256 * 256; i += stride) {
        int j = i >> 8, k = i & 255;
        g_W1eT[i] = W1[k * 768 + 512 + j];
    }
    for (int i = tid; i < 128 * 256; i += stride) {
        int j2 = i >> 8, k = i & 255;
        int j0 = j2 * 2, j1 = j0 + 1;
        __half2 a = __floats2half2_rn(Whh[k * 256 + j0],         Whh[(k + 256) * 256 + j0]);
        __half2 b = __floats2half2_rn(Whh[(k + 512) * 256 + j0], Whh[(k + 768) * 256 + j0]);
        __half2 c = __floats2half2_rn(Whh[k * 256 + j1],         Whh[(k + 256) * 256 + j1]);
        __half2 d = __floats2half2_rn(Whh[(k + 512) * 256 + j1], Whh[(k + 768) * 256 + j1]);
        uint4 u; u.x = *(unsigned*)&a; u.y = *(unsigned*)&b;
        u.z = *(unsigned*)&c; u.w = *(unsigned*)&d;
        g_WhhH[i] = u;
    }
    for (int i = tid; i < 256; i += stride) {
        g_bih4[i] = make_float4(bih[i] + bhh[i], bih[i + 256] + bhh[i + 256],
                                bih[i + 512] + bhh[i + 512], bih[i + 768] + bhh[i + 768]);
        g_wih4[i] = make_float4(Wih[i], Wih[i + 256], Wih[i + 512], Wih[i + 768]);
    }
    const int n = TB * TM1 * ENCD;
    for (int i = tid; i < n; i += stride) g_encH[i] = __float2half(enc[i]);
}

// ---------------- E = enc @ W_e^T + b_attn1 (fp16 out) ----------------------
__global__ __launch_bounds__(256) void e_gemm(const float* __restrict__ A,
                                              const float* __restrict__ bias) {
    __shared__ float As[16][64];
    __shared__ float Bs[16][64];
    const int tid = threadIdx.x;
    const int row0 = blockIdx.x * 64;
    const int col0 = blockIdx.y * 64;
    const int tx = tid & 15, ty = tid >> 4;
    float acc[4][4] = {};
    for (int k0 = 0; k0 < 256; k0 += 16) {
        #pragma unroll
        for (int i = tid; i < 1024; i += 256) {
            int m = i >> 4, kk = i & 15;
            As[kk][m] = A[(size_t)(row0 + m) * 256 + k0 + kk];
        }
        {
            int kk = tid >> 4, n4 = tid & 15;
            ((float4*)&Bs[kk][0])[n4] =
                ((const float4*)&g_W1eT[(k0 + kk) * 256 + col0])[n4];
        }
        __syncthreads();
        #pragma unroll
        for (int kk = 0; kk < 16; kk++) {
            float4 av = ((const float4*)&As[kk][0])[ty];
            float4 bv = ((const float4*)&Bs[kk][0])[tx];
            acc[0][0] += av.x * bv.x; acc[0][1] += av.x * bv.y; acc[0][2] += av.x * bv.z; acc[0][3] += av.x * bv.w;
            acc[1][0] += av.y * bv.x; acc[1][1] += av.y * bv.y; acc[1][2] += av.y * bv.z; acc[1][3] += av.y * bv.w;
            acc[2][0] += av.z * bv.x; acc[2][1] += av.z * bv.y; acc[2][2] += av.z * bv.z; acc[2][3] += av.z * bv.w;
            acc[3][0] += av.w * bv.x; acc[3][1] += av.w * bv.y; acc[3][2] += av.w * bv.z; acc[3][3] += av.w * bv.w;
        }
        __syncthreads();
    }
    float4 bv = ((const float4*)(bias + col0))[tx];
    #pragma unroll
    for (int i = 0; i < 4; i++) {
        int row = row0 + ty * 4 + i;
        __half2 h01 = __floats2half2_rn(acc[i][0] + bv.x, acc[i][1] + bv.y);
        __half2 h23 = __floats2half2_rn(acc[i][2] + bv.z, acc[i][3] + bv.w);
        uint2 u; u.x = *(unsigned*)&h01; u.y = *(unsigned*)&h23;
        ((uint2*)(g_EH + (size_t)row * 256 + col0))[tx] = u;
    }
}

// ---------------- persistent decoder: 1 CTA = 4 batch rows, 512 threads -----
__global__ __launch_bounds__(512, 1) void decoder_kernel(
    const float* __restrict__ yhist, const float* __restrict__ w2,
    const float* __restrict__ Wfc, const float* __restrict__ bfc,
    const float* __restrict__ Wfcf, const float* __restrict__ bfcf,
    float* __restrict__ out) {
    __shared__ float  shc[GB][512];    // [g][0:256]=h, [256:512]=c
    __shared__ float  sphc[GB][256];
    __shared__ float  sctx[GB][256];
    __shared__ float  sattn[GB][128];
    __shared__ float4 sbuf4[1024];     // 16KB phase-local scratch
    __shared__ float  w2s[256], wfcs[256];
    __shared__ float  sy[GB];

    const int tid = threadIdx.x;
    const int lane = tid & 31, warp = tid >> 5;
    const int k = tid & 255, half = tid >> 8;
    const int bs = blockIdx.x * GB;

    if (tid < 256) { w2s[tid] = w2[tid]; wfcs[tid] = Wfc[tid]; }
    #pragma unroll
    for (int g = 0; g < GB; g++) shc[g][tid] = 0.f;
    const float wfc_y = Wfc[256];
    const float bfc_v = bfc[0];
    __syncthreads();

    for (int step = 0; step < TM1; step++) {
        // -------- Phase A: phc[g][k] = W1_hc[k,:].[h;c], j split by half -----
        {
            unsigned long long a2[GB] = {0ull, 0ull, 0ull, 0ull};
            const uint2* Wp = g_W1h + (half << 14) + k;
            #pragma unroll 4
            for (int j = 0; j < 64; j++) {
                uint2 w = Wp[j << 8];
                float2 w01 = h2f(w.x), w23 = h2f(w.y);
                unsigned long long W01 = pk2(w01.x, w01.y), W23 = pk2(w23.x, w23.y);
                #pragma unroll
                for (int g = 0; g < GB; g++) {
                    float4 x = ((const float4*)shc[g])[(half << 6) + j];
                    fma2(a2[g], W01, pk2(x.x, x.y));
                    fma2(a2[g], W23, pk2(x.z, x.w));
                }
            }
            float a[GB];
            #pragma unroll
            for (int g = 0; g < GB; g++) { float2 f = up2(a2[g]); a[g] = f.x + f.y; }
            if (half) {
                #pragma unroll
                for (int g = 0; g < GB; g++) ((float*)sbuf4)[(g << 8) + k] = a[g];
            }
            __syncthreads();
            if (!half) {
                #pragma unroll
                for (int g = 0; g < GB; g++) sphc[g][k] = a[g] + ((float*)sbuf4)[(g << 8) + k];
            }
            __syncthreads();
        }
        // -------- Phase B: scores[g][t] = sum_k w2_k tanh(phc + E) -----------
        for (int t = warp; t < TM1; t += 16) {
            const uint2* Ev = (const uint2*)(g_EH + ((size_t)bs * TM1 + t) * 256);
            float s[GB] = {0.f, 0.f, 0.f, 0.f};
            #pragma unroll
            for (int it = 0; it < 2; it++) {
                int q = lane + (it << 5);
                float4 wv = ((const float4*)w2s)[q];
                #pragma unroll
                for (int g = 0; g < GB; g++) {
                    uint2 e = Ev[g * (TM1 * 64) + q];
                    float2 e01 = h2f(e.x), e23 = h2f(e.y);
                    float4 p = ((const float4*)sphc[g])[q];
                    s[g] += wv.x * tanh_fast(p.x + e01.x) + wv.y * tanh_fast(p.y + e01.y)
                          + wv.z * tanh_fast(p.z + e23.x) + wv.w * tanh_fast(p.w + e23.y);
                }
            }
            #pragma unroll
            for (int o = 16; o; o >>= 1) {
                #pragma unroll
                for (int g = 0; g < GB; g++)
                    s[g] += __shfl_xor_sync(0xffffffffu, s[g], o);
            }
            if (lane == 0) {
                #pragma unroll
                for (int g = 0; g < GB; g++) sattn[g][t] = s[g];
            }
        }
        __syncthreads();
        // -------- Phase C1: softmax over t + write attention output ----------
        if (warp < GB) {
            const int g = warp;
            float m = -1e30f;
            for (int t = lane; t < TM1; t += 32) m = fmaxf(m, sattn[g][t]);
            #pragma unroll
            for (int o = 16; o; o >>= 1) m = fmaxf(m, __shfl_xor_sync(0xffffffffu, m, o));
            float sum = 0.f;
            for (int t = lane; t < TM1; t += 32) {
                float e = __expf(sattn[g][t] - m); sattn[g][t] = e; sum += e;
            }
            #pragma unroll
            for (int o = 16; o; o >>= 1) sum += __shfl_xor_sync(0xffffffffu, sum, o);
            const float inv = 1.f / sum;
            float* wrow = out + TB + ((size_t)(bs + g) * TM1 + step) * TM1;
            for (int t = lane; t < TM1; t += 32) {
                float a = sattn[g][t] * inv; sattn[g][t] = a; wrow[t] = a;
            }
        }
        __syncthreads();
        // -------- Phase C2: context[g][e] = sum_t attn * enc, t split --------
        {
            const int g = tid >> 7, r = tid & 127, q = r & 63, th = r >> 6;
            const uint2* ev = (const uint2*)(g_encH + ((size_t)(bs + g) * TM1) * 256) + q;
            unsigned long long acc01 = 0ull, acc23 = 0ull;
            const int t0 = th << 6, t1 = th ? TM1 : 64;
            for (int t = t0; t < t1; t++) {
                float a = sattn[g][t];
                uint2 v = ev[(size_t)t << 6];
                float2 v01 = h2f(v.x), v23 = h2f(v.y);
                unsigned long long A = pk2(a, a);
                fma2(acc01, A, pk2(v01.x, v01.y));
                fma2(acc23, A, pk2(v23.x, v23.y));
            }
            float2 a01 = up2(acc01), a23 = up2(acc23);
            sbuf4[tid] = make_float4(a01.x, a01.y, a23.x, a23.y);
            __syncthreads();
            if (!th) {
                float4 o = sbuf4[tid], p = sbuf4[tid + 64];
                ((float4*)sctx[g])[q] =
                    make_float4(o.x + p.x, o.y + p.y, o.z + p.z, o.w + p.w);
            }
            __syncthreads();
        }
        // -------- y_tilde per g ----------------------------------------------
        #pragma unroll
        for (int g = 0; g < GB; g++) {
            float tot = blockReduceSum(tid < 256 ? wfcs[tid] * sctx[g][tid] : 0.f);
            if (tid == 0)
                sy[g] = bfc_v + wfc_y * yhist[(bs + g) * TM1 + step] + tot;
        }
        __syncthreads();
        // -------- Phase D: LSTM gates + state update, j split by half --------
        {
            unsigned long long aIF[GB] = {0ull, 0ull, 0ull, 0ull};
            unsigned long long aGO[GB] = {0ull, 0ull, 0ull, 0ull};
            const uint4* Wp = g_WhhH + (half << 14) + k;
            #pragma unroll 2
            for (int j2 = 0; j2 < 64; j2++) {
                uint4 w = Wp[j2 << 8];
                float2 wIF0 = h2f(w.x), wGO0 = h2f(w.y);
                float2 wIF1 = h2f(w.z), wGO1 = h2f(w.w);
                unsigned long long WIF0 = pk2(wIF0.x, wIF0.y), WGO0 = pk2(wGO0.x, wGO0.y);
                unsigned long long WIF1 = pk2(wIF1.x, wIF1.y), WGO1 = pk2(wGO1.x, wGO1.y);
                #pragma unroll
                for (int g = 0; g < GB; g++) {
                    float2 h = ((const float2*)shc[g])[(half << 6) + j2];
                    unsigned long long H0 = pk2(h.x, h.x), H1 = pk2(h.y, h.y);
                    fma2(aIF[g], WIF0, H0); fma2(aGO[g], WGO0, H0);
                    fma2(aIF[g], WIF1, H1); fma2(aGO[g], WGO1, H1);
                }
            }
            if (half) {
                #pragma unroll
                for (int g = 0; g < GB; g++) {
                    float2 f1 = up2(aIF[g]), f2v = up2(aGO[g]);
                    sbuf4[(g << 8) + k] = make_float4(f1.x, f1.y, f2v.x, f2v.y);
                }
            }
            __syncthreads();
            if (!half) {
                const float4 b4 = g_bih4[k], wi4 = g_wih4[k];
                #pragma unroll
                for (int g = 0; g < GB; g++) {
                    float2 fIF = up2(aIF[g]), fGO = up2(aGO[g]);
                    float4 p = sbuf4[(g << 8) + k];
                    float y = sy[g];
                    float gi = b4.x + wi4.x * y + fIF.x + p.x;
                    float gf = b4.y + wi4.y * y + fIF.y + p.y;
                    float gg = b4.z + wi4.z * y + fGO.x + p.z;
                    float go = b4.w + wi4.w * y + fGO.y + p.w;
                    float cold = shc[g][256 + k];
                    float cn = sigm(gf) * cold + sigm(gi) * tanh_acc(gg);
                    shc[g][256 + k] = cn;
                    shc[g][k] = sigm(go) * tanh_acc(cn);
                }
            }
            __syncthreads();
        }
    }
    // -------- final: out[b] = b_fcf + Wfcf . [h ; context] -------------------
    #pragma unroll
    for (int g = 0; g < GB; g++) {
        float tot = blockReduceSum(
            tid < 256 ? Wfcf[tid] * shc[g][tid] + Wfcf[256 + tid] * sctx[g][tid] : 0.f);
        if (tid == 0) out[bs + g] = bfcf[0] + tot;
    }
}

// ---------------- launch -----------------------------------------------------
extern "C" void kernel_launch(void* const* d_in, const int* in_sizes, int n_in,
                              void* d_out, int out_size) {
    const float* enc  = (const float*)d_in[0];
    const float* yh   = (const float*)d_in[1];
    const float* W1   = (const float*)d_in[2];
    const float* b1   = (const float*)d_in[3];
    const float* W2   = (const float*)d_in[4];
    // d_in[5] = b_attn2: softmax-invariant, unused
    const float* Wih  = (const float*)d_in[6];
    const float* Whh  = (const float*)d_in[7];
    const float* bih  = (const float*)d_in[8];
    const float* bhh  = (const float*)d_in[9];
    const float* Wfc  = (const float*)d_in[10];
    const float* bfc  = (const float*)d_in[11];
    const float* Wfcf = (const float*)d_in[12];
    const float* bfcf = (const float*)d_in[13];
    float* out = (float*)d_out;

    prep_kernel<<<256, 256>>>(W1, Whh, bih, bhh, Wih, enc);
    e_gemm<<<dim3(1016, 4), 256>>>(enc, b1);
    decoder_kernel<<<NCTA, 512>>>(yh, W2, Wfc, bfc, Wfcf, bfcf, out);
}

// round 3
// speedup vs baseline: 3.0683x; 1.0362x over previous
#include <cuda_runtime.h>
#include <cuda_fp16.h>
#include <cstdint>

#define TB   512
#define TM1  127
#define ENCD 256
#define GB   4
#define NCTA (TB / GB)   // 128
#define NCA  56          // W1h chunks cached in smem (of 128)
#define NCB  22          // Whh chunks cached in smem (of 128)

// ---------------- scratch (static device globals) ---------------------------
static __device__ __half g_EH[TB * TM1 * ENCD];    // E[b,t,k] fp16  (~33 MB)
static __device__ __half g_encH[TB * TM1 * ENCD];  // enc fp16       (~33 MB)
static __device__ uint2  g_W1h[128 * 256];         // (jb,k): 4 fp16 of W1hc[k][4jb..]
static __device__ uint4  g_WhhH[128 * 256];        // (j2,k): gates(i,f | g,o) fp16 for j0,j1
static __device__ float  g_W1eT[256 * 256];        // [j][k]: W_attn1[k][512+j]
static __device__ float4 g_bih4[256];              // b_ih+b_hh per gate
static __device__ float4 g_wih4[256];              // W_ih per gate

// ---------------- dynamic smem layout ---------------------------------------
struct SmemT {
    uint4  sWh[NCB * 256];      // 90112 B
    uint2  sW1[NCA * 256];      // 114688 B
    float  shc[GB][512];        // h | c
    float  sphc[GB][256];
    float  sctx[GB][256];
    float  sattn[GB][128];
    float  w2s[256];
    float  wfcs[256];
    float  syh[GB][128];
    float  spart[16];
    float  sred[16];
};

// ---------------- math helpers ----------------------------------------------
__device__ __forceinline__ float tanh_fast(float x) {
    float y; asm("tanh.approx.f32 %0, %1;" : "=f"(y) : "f"(x)); return y;
}
__device__ __forceinline__ float sigm(float x) { return 1.f / (1.f + __expf(-x)); }
__device__ __forceinline__ float tanh_acc(float x) {
    float e = __expf(2.f * x); return 1.f - 2.f / (e + 1.f);
}
__device__ __forceinline__ unsigned long long pk2(float x, float y) {
    unsigned long long r; asm("mov.b64 %0, {%1,%2};" : "=l"(r) : "f"(x), "f"(y)); return r;
}
__device__ __forceinline__ void fma2(unsigned long long& d, unsigned long long a,
                                     unsigned long long b) {
    asm("fma.rn.f32x2 %0, %1, %2, %0;" : "+l"(d) : "l"(a), "l"(b));
}
__device__ __forceinline__ float2 up2(unsigned long long v) {
    float2 f; asm("mov.b64 {%0,%1}, %2;" : "=f"(f.x), "=f"(f.y) : "l"(v)); return f;
}
__device__ __forceinline__ float2 h2f(unsigned u) {
    return __half22float2(*(__half2*)&u);
}
__device__ __forceinline__ void barn(int id) {
    asm volatile("bar.sync %0, %1;" :: "r"(id), "r"(256) : "memory");
}

// ---------------- prep: packing / fp16 conversion ---------------------------
__global__ void prep_kernel(const float* __restrict__ W1, const float* __restrict__ Whh,
                            const float* __restrict__ bih, const float* __restrict__ bhh,
                            const float* __restrict__ Wih, const float* __restrict__ enc) {
    const int tid = blockIdx.x * blockDim.x + threadIdx.x;
    const int stride = gridDim.x * blockDim.x;
    for (int i = tid; i < 128 * 256; i += stride) {
        int jb = i >> 8, k = i & 255;
        const float* p = W1 + k * 768 + jb * 4;
        __half2 a = __floats2half2_rn(p[0], p[1]);
        __half2 b = __floats2half2_rn(p[2], p[3]);
        uint2 u; u.x = *(unsigned*)&a; u.y = *(unsigned*)&b;
        g_W1h[i] = u;
    }
    for (int i = tid; i < 256 * 256; i += stride) {
        int j = i >> 8, k = i & 255;
        g_W1eT[i] = W1[k * 768 + 512 + j];
    }
    for (int i = tid; i < 128 * 256; i += stride) {
        int j2 = i >> 8, k = i & 255;
        int j0 = j2 * 2, j1 = j0 + 1;
        __half2 a = __floats2half2_rn(Whh[k * 256 + j0],         Whh[(k + 256) * 256 + j0]);
        __half2 b = __floats2half2_rn(Whh[(k + 512) * 256 + j0], Whh[(k + 768) * 256 + j0]);
        __half2 c = __floats2half2_rn(Whh[k * 256 + j1],         Whh[(k + 256) * 256 + j1]);
        __half2 d = __floats2half2_rn(Whh[(k + 512) * 256 + j1], Whh[(k + 768) * 256 + j1]);
        uint4 u; u.x = *(unsigned*)&a; u.y = *(unsigned*)&b;
        u.z = *(unsigned*)&c; u.w = *(unsigned*)&d;
        g_WhhH[i] = u;
    }
    for (int i = tid; i < 256; i += stride) {
        g_bih4[i] = make_float4(bih[i] + bhh[i], bih[i + 256] + bhh[i + 256],
                                bih[i + 512] + bhh[i + 512], bih[i + 768] + bhh[i + 768]);
        g_wih4[i] = make_float4(Wih[i], Wih[i + 256], Wih[i + 512], Wih[i + 768]);
    }
    const int n = TB * TM1 * ENCD;
    for (int i = tid; i < n; i += stride) g_encH[i] = __float2half(enc[i]);
}

// ---------------- E = enc @ W_e^T + b_attn1 (fp16 out) ----------------------
__global__ __launch_bounds__(256) void e_gemm(const float* __restrict__ A,
                                              const float* __restrict__ bias) {
    __shared__ float As[16][64];
    __shared__ float Bs[16][64];
    const int tid = threadIdx.x;
    const int row0 = blockIdx.x * 64;
    const int col0 = blockIdx.y * 64;
    const int tx = tid & 15, ty = tid >> 4;
    float acc[4][4] = {};
    for (int k0 = 0; k0 < 256; k0 += 16) {
        #pragma unroll
        for (int i = tid; i < 1024; i += 256) {
            int m = i >> 4, kk = i & 15;
            As[kk][m] = A[(size_t)(row0 + m) * 256 + k0 + kk];
        }
        {
            int kk = tid >> 4, n4 = tid & 15;
            ((float4*)&Bs[kk][0])[n4] =
                ((const float4*)&g_W1eT[(k0 + kk) * 256 + col0])[n4];
        }
        __syncthreads();
        #pragma unroll
        for (int kk = 0; kk < 16; kk++) {
            float4 av = ((const float4*)&As[kk][0])[ty];
            float4 bv = ((const float4*)&Bs[kk][0])[tx];
            acc[0][0] += av.x * bv.x; acc[0][1] += av.x * bv.y; acc[0][2] += av.x * bv.z; acc[0][3] += av.x * bv.w;
            acc[1][0] += av.y * bv.x; acc[1][1] += av.y * bv.y; acc[1][2] += av.y * bv.z; acc[1][3] += av.y * bv.w;
            acc[2][0] += av.z * bv.x; acc[2][1] += av.z * bv.y; acc[2][2] += av.z * bv.z; acc[2][3] += av.z * bv.w;
            acc[3][0] += av.w * bv.x; acc[3][1] += av.w * bv.y; acc[3][2] += av.w * bv.z; acc[3][3] += av.w * bv.w;
        }
        __syncthreads();
    }
    float4 bv = ((const float4*)(bias + col0))[tx];
    #pragma unroll
    for (int i = 0; i < 4; i++) {
        int row = row0 + ty * 4 + i;
        __half2 h01 = __floats2half2_rn(acc[i][0] + bv.x, acc[i][1] + bv.y);
        __half2 h23 = __floats2half2_rn(acc[i][2] + bv.z, acc[i][3] + bv.w);
        uint2 u; u.x = *(unsigned*)&h01; u.y = *(unsigned*)&h23;
        ((uint2*)(g_EH + (size_t)row * 256 + col0))[tx] = u;
    }
}

// ---------------- persistent decoder: warp-specialized, 512 threads ---------
__global__ __launch_bounds__(512, 1) void decoder_kernel(
    const float* __restrict__ yhist, const float* __restrict__ w2,
    const float* __restrict__ Wfc, const float* __restrict__ bfc,
    const float* __restrict__ Wfcf, const float* __restrict__ bfcf,
    float* __restrict__ out) {
    extern __shared__ char smem_raw[];
    SmemT& s = *(SmemT*)smem_raw;

    const int tid = threadIdx.x;
    const int lane = tid & 31, warp = tid >> 5;
    const int bs = blockIdx.x * GB;
    const bool is_attn = tid < 256;
    const int k = tid & 255;

    // ---- init: caches, state, small tables ---------------------------------
    for (int i = tid; i < NCA * 256; i += 512) s.sW1[i] = g_W1h[i];
    for (int i = tid; i < NCB * 256; i += 512) s.sWh[i] = g_WhhH[i];
    {   // yhist rows
        int g = tid >> 7, t = tid & 127;
        if (t < TM1) s.syh[g][t] = yhist[(bs + g) * TM1 + t];
    }
    if (is_attn) { s.w2s[k] = w2[k]; s.wfcs[k] = Wfc[k]; }
    #pragma unroll
    for (int g = 0; g < GB; g++) { if (is_attn) { s.shc[g][k] = 0.f; s.shc[g][256 + k] = 0.f; } }
    const float wfc_y = Wfc[256];
    const float bfc_v = bfc[0];
    float4 b4, wi4;
    if (!is_attn) { b4 = g_bih4[k]; wi4 = g_wih4[k]; }
    __syncthreads();

    for (int step = 0; step < TM1; step++) {
        if (is_attn) {
            // ---- Phase A: phc[g][k] = W1_hc[k,:].[h;c] ----------------------
            unsigned long long a2[GB] = {0ull, 0ull, 0ull, 0ull};
            #pragma unroll 4
            for (int jb = 0; jb < NCA; jb++) {
                uint2 w = s.sW1[(jb << 8) + k];
                float2 w01 = h2f(w.x), w23 = h2f(w.y);
                unsigned long long W01 = pk2(w01.x, w01.y), W23 = pk2(w23.x, w23.y);
                #pragma unroll
                for (int g = 0; g < GB; g++) {
                    float4 x = ((const float4*)s.shc[g])[jb];
                    fma2(a2[g], W01, pk2(x.x, x.y));
                    fma2(a2[g], W23, pk2(x.z, x.w));
                }
            }
            #pragma unroll 8
            for (int jb = NCA; jb < 128; jb++) {
                uint2 w = g_W1h[(jb << 8) + k];
                float2 w01 = h2f(w.x), w23 = h2f(w.y);
                unsigned long long W01 = pk2(w01.x, w01.y), W23 = pk2(w23.x, w23.y);
                #pragma unroll
                for (int g = 0; g < GB; g++) {
                    float4 x = ((const float4*)s.shc[g])[jb];
                    fma2(a2[g], W01, pk2(x.x, x.y));
                    fma2(a2[g], W23, pk2(x.z, x.w));
                }
            }
            #pragma unroll
            for (int g = 0; g < GB; g++) { float2 f = up2(a2[g]); s.sphc[g][k] = f.x + f.y; }
            barn(1);
            // ---- Phase B: scores[g][t] -------------------------------------
            for (int t = warp; t < TM1; t += 8) {
                const uint2* Ev = (const uint2*)(g_EH + ((size_t)bs * TM1 + t) * 256);
                float sc[GB] = {0.f, 0.f, 0.f, 0.f};
                #pragma unroll
                for (int it = 0; it < 2; it++) {
                    int q = lane + (it << 5);
                    float4 wv = ((const float4*)s.w2s)[q];
                    #pragma unroll
                    for (int g = 0; g < GB; g++) {
                        uint2 e = Ev[g * (TM1 * 64) + q];
                        float2 e01 = h2f(e.x), e23 = h2f(e.y);
                        float4 p = ((const float4*)s.sphc[g])[q];
                        sc[g] += wv.x * tanh_fast(p.x + e01.x) + wv.y * tanh_fast(p.y + e01.y)
                               + wv.z * tanh_fast(p.z + e23.x) + wv.w * tanh_fast(p.w + e23.y);
                    }
                }
                #pragma unroll
                for (int o = 16; o; o >>= 1) {
                    #pragma unroll
                    for (int g = 0; g < GB; g++)
                        sc[g] += __shfl_xor_sync(0xffffffffu, sc[g], o);
                }
                if (lane == 0) {
                    #pragma unroll
                    for (int g = 0; g < GB; g++) s.sattn[g][t] = sc[g];
                }
            }
            barn(1);
            // ---- Phase C1: softmax + write attention rows -------------------
            if (warp < GB) {
                const int g = warp;
                float m = -1e30f;
                for (int t = lane; t < TM1; t += 32) m = fmaxf(m, s.sattn[g][t]);
                #pragma unroll
                for (int o = 16; o; o >>= 1) m = fmaxf(m, __shfl_xor_sync(0xffffffffu, m, o));
                float sum = 0.f;
                for (int t = lane; t < TM1; t += 32) {
                    float e = __expf(s.sattn[g][t] - m); s.sattn[g][t] = e; sum += e;
                }
                #pragma unroll
                for (int o = 16; o; o >>= 1) sum += __shfl_xor_sync(0xffffffffu, sum, o);
                const float inv = 1.f / sum;
                float* wrow = out + TB + ((size_t)(bs + g) * TM1 + step) * TM1;
                for (int t = lane; t < TM1; t += 32) {
                    float a = s.sattn[g][t] * inv; s.sattn[g][t] = a; wrow[t] = a;
                }
            }
        } else {
            // ---- Phase D matvec (concurrent with A/B/C1): gates += Whh@h ----
            unsigned long long aIF[GB] = {0ull, 0ull, 0ull, 0ull};
            unsigned long long aGO[GB] = {0ull, 0ull, 0ull, 0ull};
            #pragma unroll 2
            for (int j2 = 0; j2 < NCB; j2++) {
                uint4 w = s.sWh[(j2 << 8) + k];
                float2 wIF0 = h2f(w.x), wGO0 = h2f(w.y);
                float2 wIF1 = h2f(w.z), wGO1 = h2f(w.w);
                unsigned long long WIF0 = pk2(wIF0.x, wIF0.y), WGO0 = pk2(wGO0.x, wGO0.y);
                unsigned long long WIF1 = pk2(wIF1.x, wIF1.y), WGO1 = pk2(wGO1.x, wGO1.y);
                #pragma unroll
                for (int g = 0; g < GB; g++) {
                    float2 h = ((const float2*)s.shc[g])[j2];
                    unsigned long long H0 = pk2(h.x, h.x), H1 = pk2(h.y, h.y);
                    fma2(aIF[g], WIF0, H0); fma2(aGO[g], WGO0, H0);
                    fma2(aIF[g], WIF1, H1); fma2(aGO[g], WGO1, H1);
                }
            }
            #pragma unroll 4
            for (int j2 = NCB; j2 < 128; j2++) {
                uint4 w = g_WhhH[(j2 << 8) + k];
                float2 wIF0 = h2f(w.x), wGO0 = h2f(w.y);
                float2 wIF1 = h2f(w.z), wGO1 = h2f(w.w);
                unsigned long long WIF0 = pk2(wIF0.x, wIF0.y), WGO0 = pk2(wGO0.x, wGO0.y);
                unsigned long long WIF1 = pk2(wIF1.x, wIF1.y), WGO1 = pk2(wGO1.x, wGO1.y);
                #pragma unroll
                for (int g = 0; g < GB; g++) {
                    float2 h = ((const float2*)s.shc[g])[j2];
                    unsigned long long H0 = pk2(h.x, h.x), H1 = pk2(h.y, h.y);
                    fma2(aIF[g], WIF0, H0); fma2(aGO[g], WGO0, H0);
                    fma2(aIF[g], WIF1, H1); fma2(aGO[g], WGO1, H1);
                }
            }
            __syncthreads();   // [#1] join: sattn ready (attn), h reads done (lstm)
            // ---- Phase C2: context[g][e] = sum_t attn*enc -------------------
            {
                const int r = tid & 255, g = r >> 6, q = r & 63;
                const uint2* ev = (const uint2*)(g_encH + ((size_t)(bs + g) * TM1) * 256) + q;
                unsigned long long acc01 = 0ull, acc23 = 0ull;
                #pragma unroll 4
                for (int t = 0; t < TM1; t++) {
                    float a = s.sattn[g][t];
                    uint2 v = ev[(size_t)t << 6];
                    float2 v01 = h2f(v.x), v23 = h2f(v.y);
                    unsigned long long A = pk2(a, a);
                    fma2(acc01, A, pk2(v01.x, v01.y));
                    fma2(acc23, A, pk2(v23.x, v23.y));
                }
                float2 a01 = up2(acc01), a23 = up2(acc23);
                ((float4*)s.sctx[g])[q] = make_float4(a01.x, a01.y, a23.x, a23.y);
            }
            barn(2);
            // ---- y partials: spart[w] = dot(wfcs, ctx) halves ---------------
            {
                const int lw = warp - 8, g = lw >> 1, hf = lw & 1;
                const int idx = (hf << 5) + lane;
                float4 wv = ((const float4*)s.wfcs)[idx];
                float4 cv = ((const float4*)s.sctx[g])[idx];
                float v = wv.x * cv.x + wv.y * cv.y + wv.z * cv.z + wv.w * cv.w;
                #pragma unroll
                for (int o = 16; o; o >>= 1) v += __shfl_xor_sync(0xffffffffu, v, o);
                if (lane == 0) s.spart[lw] = v;
            }
            barn(2);
            // ---- combine: gates + y, update h,c -----------------------------
            #pragma unroll
            for (int g = 0; g < GB; g++) {
                float y = bfc_v + wfc_y * s.syh[g][step] + s.spart[2 * g] + s.spart[2 * g + 1];
                float2 fIF = up2(aIF[g]), fGO = up2(aGO[g]);
                float gi = b4.x + wi4.x * y + fIF.x;
                float gf = b4.y + wi4.y * y + fIF.y;
                float gg = b4.z + wi4.z * y + fGO.x;
                float go = b4.w + wi4.w * y + fGO.y;
                float cold = s.shc[g][256 + k];
                float cn = sigm(gf) * cold + sigm(gi) * tanh_acc(gg);
                s.shc[g][256 + k] = cn;
                s.shc[g][k] = sigm(go) * tanh_acc(cn);
            }
        }
        if (is_attn) {
            __syncthreads();   // [#1] (attn side)
        }
        __syncthreads();       // [#2] h,c / sctx updated for next step
    }
    // ---- final: out[b] = b_fcf + Wfcf . [h ; context] -----------------------
    #pragma unroll
    for (int g = 0; g < GB; g++) {
        float v = is_attn ? (Wfcf[k] * s.shc[g][k] + Wfcf[256 + k] * s.sctx[g][k]) : 0.f;
        #pragma unroll
        for (int o = 16; o; o >>= 1) v += __shfl_down_sync(0xffffffffu, v, o);
        if (lane == 0) s.sred[warp] = v;
        __syncthreads();
        if (warp == 0) {
            float r = (lane < 16) ? s.sred[lane] : 0.f;
            #pragma unroll
            for (int o = 8; o; o >>= 1) r += __shfl_down_sync(0xffffffffu, r, o);
            if (lane == 0) out[bs + g] = bfcf[0] + r;
        }
        __syncthreads();
    }
}

// ---------------- launch -----------------------------------------------------
extern "C" void kernel_launch(void* const* d_in, const int* in_sizes, int n_in,
                              void* d_out, int out_size) {
    const float* enc  = (const float*)d_in[0];
    const float* yh   = (const float*)d_in[1];
    const float* W1   = (const float*)d_in[2];
    const float* b1   = (const float*)d_in[3];
    const float* W2   = (const float*)d_in[4];
    // d_in[5] = b_attn2: softmax-invariant, unused
    const float* Wih  = (const float*)d_in[6];
    const float* Whh  = (const float*)d_in[7];
    const float* bih  = (const float*)d_in[8];
    const float* bhh  = (const float*)d_in[9];
    const float* Wfc  = (const float*)d_in[10];
    const float* bfc  = (const float*)d_in[11];
    const float* Wfcf = (const float*)d_in[12];
    const float* bfcf = (const float*)d_in[13];
    float* out = (float*)d_out;

    static bool attr_done = false;
    if (!attr_done) {
        cudaFuncSetAttribute(decoder_kernel,
                             cudaFuncAttributeMaxDynamicSharedMemorySize, sizeof(SmemT));
        attr_done = true;
    }
    prep_kernel<<<256, 256>>>(W1, Whh, bih, bhh, Wih, enc);
    e_gemm<<<dim3(1016, 4), 256>>>(enc, b1);
    decoder_kernel<<<NCTA, 512, sizeof(SmemT)>>>(yh, W2, Wfc, bfc, Wfcf, bfcf, out);
}

// round 4
// speedup vs baseline: 3.1613x; 1.0303x over previous
#include <cuda_runtime.h>
#include <cuda_fp16.h>
#include <cstdint>

#define TB   512
#define TM1  127
#define ENCD 256
#define GB   4
#define NCTA (TB / GB)   // 128
#define NCA  23          // W1h chunks cached in smem (of 128)
#define NCB  32          // Whh chunks cached in smem (of 128)

typedef unsigned long long ull;

// ---------------- scratch (static device globals) ---------------------------
static __device__ __half g_EH[TB * TM1 * ENCD];    // E[b,t,k] fp16  (~33 MB)
static __device__ __half g_encH[TB * TM1 * ENCD];  // enc fp16       (~33 MB)
static __device__ uint2  g_W1h[128 * 256];         // (jb,k): 4 fp16 of W1hc[k][4jb..]
static __device__ uint4  g_WhhH[128 * 256];        // (j2,k): half2 (IF_j0,GO_j0,IF_j1,GO_j1)
static __device__ float  g_W1eT[256 * 256];        // [j][k]: W_attn1[k][512+j]
static __device__ float4 g_bih4[256];              // b_ih+b_hh per gate
static __device__ float4 g_wih4[256];              // W_ih per gate

// ---------------- dynamic smem layout ---------------------------------------
struct SmemT {
    uint4    sWh[NCB * 256];     // 131072
    uint2    sW1[NCA * 256];     // 47104
    float4   sbufA[1024];        // 16384 : A partials (float view) / D exchange
    float4   sbufC[512];         // 8192  : C2 partials
    float    shc[GB][512];       // 8192  : h | c (f32)
    float    sphc[GB][256];      // 4096
    float    sctx[GB][256];      // 4096
    float    sattn[GB][128];     // 2048
    unsigned shD[GB][256];       // 4096  : splat half2(h_j,h_j)
    float    w2s[256];           // 1024
    float    wfcs[256];          // 1024
    float    syh[GB][128];       // 2048
    float    spart[8];
    float    sred[32];
};

// ---------------- math helpers ----------------------------------------------
__device__ __forceinline__ float tanh_fast(float x) {
    float y; asm("tanh.approx.f32 %0, %1;" : "=f"(y) : "f"(x)); return y;
}
__device__ __forceinline__ float sigm(float x) { return 1.f / (1.f + __expf(-x)); }
__device__ __forceinline__ float tanh_acc(float x) {
    float e = __expf(2.f * x); return 1.f - 2.f / (e + 1.f);
}
__device__ __forceinline__ ull pk2(float x, float y) {
    ull r; asm("mov.b64 %0, {%1,%2};" : "=l"(r) : "f"(x), "f"(y)); return r;
}
__device__ __forceinline__ void fma2(ull& d, ull a, ull b) {
    asm("fma.rn.f32x2 %0, %1, %2, %0;" : "+l"(d) : "l"(a), "l"(b));
}
__device__ __forceinline__ float2 up2(ull v) {
    float2 f; asm("mov.b64 {%0,%1}, %2;" : "=f"(f.x), "=f"(f.y) : "l"(v)); return f;
}
__device__ __forceinline__ float2 h2f(unsigned u) {
    return __half22float2(*(__half2*)&u);
}
__device__ __forceinline__ __half2 uh2(unsigned u) { return *(__half2*)&u; }

// ---------------- prep: packing / fp16 conversion ---------------------------
__global__ void prep_kernel(const float* __restrict__ W1, const float* __restrict__ Whh,
                            const float* __restrict__ bih, const float* __restrict__ bhh,
                            const float* __restrict__ Wih, const float* __restrict__ enc) {
    const int tid = blockIdx.x * blockDim.x + threadIdx.x;
    const int stride = gridDim.x * blockDim.x;
    for (int i = tid; i < 128 * 256; i += stride) {
        int jb = i >> 8, k = i & 255;
        const float* p = W1 + k * 768 + jb * 4;
        __half2 a = __floats2half2_rn(p[0], p[1]);
        __half2 b = __floats2half2_rn(p[2], p[3]);
        uint2 u; u.x = *(unsigned*)&a; u.y = *(unsigned*)&b;
        g_W1h[i] = u;
    }
    for (int i = tid; i < 256 * 256; i += stride) {
        int j = i >> 8, k = i & 255;
        g_W1eT[i] = W1[k * 768 + 512 + j];
    }
    for (int i = tid; i < 128 * 256; i += stride) {
        int j2 = i >> 8, k = i & 255;
        int j0 = j2 * 2, j1 = j0 + 1;
        __half2 a = __floats2half2_rn(Whh[k * 256 + j0],         Whh[(k + 256) * 256 + j0]);
        __half2 b = __floats2half2_rn(Whh[(k + 512) * 256 + j0], Whh[(k + 768) * 256 + j0]);
        __half2 c = __floats2half2_rn(Whh[k * 256 + j1],         Whh[(k + 256) * 256 + j1]);
        __half2 d = __floats2half2_rn(Whh[(k + 512) * 256 + j1], Whh[(k + 768) * 256 + j1]);
        uint4 u; u.x = *(unsigned*)&a; u.y = *(unsigned*)&b;
        u.z = *(unsigned*)&c; u.w = *(unsigned*)&d;
        g_WhhH[i] = u;
    }
    for (int i = tid; i < 256; i += stride) {
        g_bih4[i] = make_float4(bih[i] + bhh[i], bih[i + 256] + bhh[i + 256],
                                bih[i + 512] + bhh[i + 512], bih[i + 768] + bhh[i + 768]);
        g_wih4[i] = make_float4(Wih[i], Wih[i + 256], Wih[i + 512], Wih[i + 768]);
    }
    const int n = TB * TM1 * ENCD;
    for (int i = tid; i < n; i += stride) g_encH[i] = __float2half(enc[i]);
}

// ---------------- E = enc @ W_e^T + b_attn1 (fp16 out) ----------------------
__global__ __launch_bounds__(256) void e_gemm(const float* __restrict__ A,
                                              const float* __restrict__ bias) {
    __shared__ float As[16][64];
    __shared__ float Bs[16][64];
    const int tid = threadIdx.x;
    const int row0 = blockIdx.x * 64;
    const int col0 = blockIdx.y * 64;
    const int tx = tid & 15, ty = tid >> 4;
    float acc[4][4] = {};
    for (int k0 = 0; k0 < 256; k0 += 16) {
        #pragma unroll
        for (int i = tid; i < 1024; i += 256) {
            int m = i >> 4, kk = i & 15;
            As[kk][m] = A[(size_t)(row0 + m) * 256 + k0 + kk];
        }
        {
            int kk = tid >> 4, n4 = tid & 15;
            ((float4*)&Bs[kk][0])[n4] =
                ((const float4*)&g_W1eT[(k0 + kk) * 256 + col0])[n4];
        }
        __syncthreads();
        #pragma unroll
        for (int kk = 0; kk < 16; kk++) {
            float4 av = ((const float4*)&As[kk][0])[ty];
            float4 bv = ((const float4*)&Bs[kk][0])[tx];
            acc[0][0] += av.x * bv.x; acc[0][1] += av.x * bv.y; acc[0][2] += av.x * bv.z; acc[0][3] += av.x * bv.w;
            acc[1][0] += av.y * bv.x; acc[1][1] += av.y * bv.y; acc[1][2] += av.y * bv.z; acc[1][3] += av.y * bv.w;
            acc[2][0] += av.z * bv.x; acc[2][1] += av.z * bv.y; acc[2][2] += av.z * bv.z; acc[2][3] += av.z * bv.w;
            acc[3][0] += av.w * bv.x; acc[3][1] += av.w * bv.y; acc[3][2] += av.w * bv.z; acc[3][3] += av.w * bv.w;
        }
        __syncthreads();
    }
    float4 bv = ((const float4*)(bias + col0))[tx];
    #pragma unroll
    for (int i = 0; i < 4; i++) {
        int row = row0 + ty * 4 + i;
        __half2 h01 = __floats2half2_rn(acc[i][0] + bv.x, acc[i][1] + bv.y);
        __half2 h23 = __floats2half2_rn(acc[i][2] + bv.z, acc[i][3] + bv.w);
        uint2 u; u.x = *(unsigned*)&h01; u.y = *(unsigned*)&h23;
        ((uint2*)(g_EH + (size_t)row * 256 + col0))[tx] = u;
    }
}

// ---------------- persistent decoder: 1024 threads, A-all then B||D ---------
__global__ __launch_bounds__(1024, 1) void decoder_kernel(
    const float* __restrict__ yhist, const float* __restrict__ w2,
    const float* __restrict__ Wfc, const float* __restrict__ bfc,
    const float* __restrict__ Wfcf, const float* __restrict__ bfcf,
    float* __restrict__ out) {
    extern __shared__ char smem_raw[];
    SmemT& s = *(SmemT*)smem_raw;

    const int tid = threadIdx.x;
    const int lane = tid & 31, warp = tid >> 5;
    const int bs = blockIdx.x * GB;
    const int k = tid & 255;

    // ---- init --------------------------------------------------------------
    for (int i = tid; i < NCA * 256; i += 1024) s.sW1[i] = g_W1h[i];
    for (int i = tid; i < NCB * 256; i += 1024) s.sWh[i] = g_WhhH[i];
    if (tid < 512) {
        int g = tid >> 7, t = tid & 127;
        if (t < TM1) s.syh[g][t] = yhist[(bs + g) * TM1 + t];
    }
    if (tid < 256) {
        s.w2s[tid] = w2[tid]; s.wfcs[tid] = Wfc[tid];
        #pragma unroll
        for (int g = 0; g < GB; g++) {
            s.shc[g][tid] = 0.f; s.shc[g][256 + tid] = 0.f; s.shD[g][tid] = 0u;
        }
    }
    const float wfc_y = Wfc[256];
    const float bfc_v = bfc[0];
    float4 b4 = make_float4(0, 0, 0, 0), wi4 = b4;
    if (tid >= 512 && tid < 768) { b4 = g_bih4[k]; wi4 = g_wih4[k]; }
    __syncthreads();

    for (int step = 0; step < TM1; step++) {
        // ==== Phase A (all 1024): phc partials, 4-way jb split ===============
        {
            const int q4 = tid >> 8;
            ull a2[GB] = {0ull, 0ull, 0ull, 0ull};
            const int iC = (NCA - q4 + 3) >> 2;
            #pragma unroll 4
            for (int i = 0; i < iC; i++) {
                int jb = q4 + 4 * i;
                uint2 w = s.sW1[(jb << 8) + k];
                float2 w01 = h2f(w.x), w23 = h2f(w.y);
                ull W01 = pk2(w01.x, w01.y), W23 = pk2(w23.x, w23.y);
                #pragma unroll
                for (int g = 0; g < GB; g++) {
                    float4 x = ((const float4*)s.shc[g])[jb];
                    fma2(a2[g], W01, pk2(x.x, x.y));
                    fma2(a2[g], W23, pk2(x.z, x.w));
                }
            }
            #pragma unroll 4
            for (int i = iC; i < 32; i++) {
                int jb = q4 + 4 * i;
                uint2 w = g_W1h[(jb << 8) + k];
                float2 w01 = h2f(w.x), w23 = h2f(w.y);
                ull W01 = pk2(w01.x, w01.y), W23 = pk2(w23.x, w23.y);
                #pragma unroll
                for (int g = 0; g < GB; g++) {
                    float4 x = ((const float4*)s.shc[g])[jb];
                    fma2(a2[g], W01, pk2(x.x, x.y));
                    fma2(a2[g], W23, pk2(x.z, x.w));
                }
            }
            #pragma unroll
            for (int g = 0; g < GB; g++) {
                float2 f = up2(a2[g]);
                ((float*)s.sbufA)[(q4 << 10) + (g << 8) + k] = f.x + f.y;
            }
        }
        __syncthreads();
        if (tid < 256) {   // A reduce -> sphc
            const float* pb = (const float*)s.sbufA;
            #pragma unroll
            for (int g = 0; g < GB; g++) {
                int o = (g << 8) + tid;
                s.sphc[g][tid] = pb[o] + pb[1024 + o] + pb[2048 + o] + pb[3072 + o];
            }
        }
        __syncthreads();

        float2 fIF[GB], fGO[GB];   // D accumulators (live in lstm-group regs)
        if (tid < 512) {
            // ==== Phase B (warps 0-15): scores ===============================
            for (int t = warp; t < TM1; t += 16) {
                const uint2* Ev = (const uint2*)(g_EH + ((size_t)bs * TM1 + t) * 256);
                float sc[GB] = {0.f, 0.f, 0.f, 0.f};
                #pragma unroll
                for (int it = 0; it < 2; it++) {
                    int q = lane + (it << 5);
                    float4 wv = ((const float4*)s.w2s)[q];
                    #pragma unroll
                    for (int g = 0; g < GB; g++) {
                        uint2 e = Ev[g * (TM1 * 64) + q];
                        float2 e01 = h2f(e.x), e23 = h2f(e.y);
                        float4 p = ((const float4*)s.sphc[g])[q];
                        sc[g] += wv.x * tanh_fast(p.x + e01.x) + wv.y * tanh_fast(p.y + e01.y)
                               + wv.z * tanh_fast(p.z + e23.x) + wv.w * tanh_fast(p.w + e23.y);
                    }
                }
                #pragma unroll
                for (int o = 16; o; o >>= 1) {
                    #pragma unroll
                    for (int g = 0; g < GB; g++)
                        sc[g] += __shfl_xor_sync(0xffffffffu, sc[g], o);
                }
                if (lane == 0) {
                    #pragma unroll
                    for (int g = 0; g < GB; g++) s.sattn[g][t] = sc[g];
                }
            }
            asm volatile("bar.sync 1, 512;" ::: "memory");
            // ==== Phase C1 (warps 0-3): softmax + write attn rows ============
            if (warp < GB) {
                const int g = warp;
                float m = -1e30f;
                for (int t = lane; t < TM1; t += 32) m = fmaxf(m, s.sattn[g][t]);
                #pragma unroll
                for (int o = 16; o; o >>= 1) m = fmaxf(m, __shfl_xor_sync(0xffffffffu, m, o));
                float sum = 0.f;
                for (int t = lane; t < TM1; t += 32) {
                    float e = __expf(s.sattn[g][t] - m); s.sattn[g][t] = e; sum += e;
                }
                #pragma unroll
                for (int o = 16; o; o >>= 1) sum += __shfl_xor_sync(0xffffffffu, sum, o);
                const float inv = 1.f / sum;
                float* wrow = out + TB + ((size_t)(bs + g) * TM1 + step) * TM1;
                for (int t = lane; t < TM1; t += 32) {
                    float a = s.sattn[g][t] * inv; s.sattn[g][t] = a; wrow[t] = a;
                }
            }
        } else {
            // ==== Phase D (warps 16-31): gates = Whh @ h, HFMA2, j-split =====
            const int jh = (tid >> 8) & 1;   // 0: even j2, 1: odd j2
            __half2 hIF[GB], hGO[GB];
            #pragma unroll
            for (int g = 0; g < GB; g++) {
                hIF[g] = __float2half2_rn(0.f); hGO[g] = __float2half2_rn(0.f);
                fIF[g] = make_float2(0.f, 0.f); fGO[g] = make_float2(0.f, 0.f);
            }
            int i = 0;
            #pragma unroll
            for (int ch = 0; ch < 2; ch++) {          // cached chunks (16 i)
                #pragma unroll
                for (int u = 0; u < 8; u++, i++) {
                    int j2 = jh + 2 * i;
                    uint4 w = s.sWh[(j2 << 8) + k];
                    #pragma unroll
                    for (int g = 0; g < GB; g++) {
                        uint2 H2 = *(const uint2*)&s.shD[g][2 * j2];
                        __half2 H0 = uh2(H2.x), H1 = uh2(H2.y);
                        hIF[g] = __hfma2(uh2(w.x), H0, hIF[g]);
                        hGO[g] = __hfma2(uh2(w.y), H0, hGO[g]);
                        hIF[g] = __hfma2(uh2(w.z), H1, hIF[g]);
                        hGO[g] = __hfma2(uh2(w.w), H1, hGO[g]);
                    }
                }
                #pragma unroll
                for (int g = 0; g < GB; g++) {
                    float2 a = __half22float2(hIF[g]), b = __half22float2(hGO[g]);
                    fIF[g].x += a.x; fIF[g].y += a.y; fGO[g].x += b.x; fGO[g].y += b.y;
                    hIF[g] = __float2half2_rn(0.f); hGO[g] = __float2half2_rn(0.f);
                }
            }
            for (int ch = 0; ch < 6; ch++) {          // streamed chunks (48 i)
                #pragma unroll
                for (int u = 0; u < 8; u++, i++) {
                    int j2 = jh + 2 * i;
                    uint4 w = g_WhhH[(j2 << 8) + k];
                    #pragma unroll
                    for (int g = 0; g < GB; g++) {
                        uint2 H2 = *(const uint2*)&s.shD[g][2 * j2];
                        __half2 H0 = uh2(H2.x), H1 = uh2(H2.y);
                        hIF[g] = __hfma2(uh2(w.x), H0, hIF[g]);
                        hGO[g] = __hfma2(uh2(w.y), H0, hGO[g]);
                        hIF[g] = __hfma2(uh2(w.z), H1, hIF[g]);
                        hGO[g] = __hfma2(uh2(w.w), H1, hGO[g]);
                    }
                }
                #pragma unroll
                for (int g = 0; g < GB; g++) {
                    float2 a = __half22float2(hIF[g]), b = __half22float2(hGO[g]);
                    fIF[g].x += a.x; fIF[g].y += a.y; fGO[g].x += b.x; fGO[g].y += b.y;
                    hIF[g] = __float2half2_rn(0.f); hGO[g] = __float2half2_rn(0.f);
                }
            }
            if (jh == 1) {   // exchange odd-half partials
                #pragma unroll
                for (int g = 0; g < GB; g++)
                    s.sbufA[(g << 8) + k] =
                        make_float4(fIF[g].x, fIF[g].y, fGO[g].x, fGO[g].y);
            }
        }
        __syncthreads();   // join: sattn ready, D partials exchanged
        // ==== Phase C2 (tid<512): context partials, 2-way t split ============
        if (tid < 512) {
            const int g = tid >> 7, q = tid & 63, th = (tid >> 6) & 1;
            const uint2* ev = (const uint2*)(g_encH + ((size_t)(bs + g) * TM1) * 256) + q;
            ull acc01 = 0ull, acc23 = 0ull;
            const int t0 = th << 6, t1 = th ? TM1 : 64;
            #pragma unroll 4
            for (int t = t0; t < t1; t++) {
                float a = s.sattn[g][t];
                uint2 v = ev[(size_t)t << 6];
                float2 v01 = h2f(v.x), v23 = h2f(v.y);
                ull A = pk2(a, a);
                fma2(acc01, A, pk2(v01.x, v01.y));
                fma2(acc23, A, pk2(v23.x, v23.y));
            }
            float2 a01 = up2(acc01), a23 = up2(acc23);
            s.sbufC[((g << 1) | th) << 6 | q] = make_float4(a01.x, a01.y, a23.x, a23.y);
        } else if (tid < 768) {
            // fold in odd-half D partials
            #pragma unroll
            for (int g = 0; g < GB; g++) {
                float4 p = s.sbufA[(g << 8) + k];
                fIF[g].x += p.x; fIF[g].y += p.y; fGO[g].x += p.z; fGO[g].y += p.w;
            }
        }
        __syncthreads();
        // ==== C2 reduce + y partials (warps 0-7) =============================
        if (warp < 8) {
            const int g = warp >> 1, hf = warp & 1;
            const int idx = (hf << 5) + lane;          // 0..63
            float4 o = s.sbufC[(g << 7) | idx];
            float4 p = s.sbufC[(g << 7) | 64 | idx];
            float4 c4 = make_float4(o.x + p.x, o.y + p.y, o.z + p.z, o.w + p.w);
            ((float4*)s.sctx[g])[idx] = c4;
            float4 wv = ((const float4*)s.wfcs)[idx];
            float v = wv.x * c4.x + wv.y * c4.y + wv.z * c4.z + wv.w * c4.w;
            #pragma unroll
            for (int o2 = 16; o2; o2 >>= 1) v += __shfl_xor_sync(0xffffffffu, v, o2);
            if (lane == 0) s.spart[(g << 1) + hf] = v;
        }
        __syncthreads();
        // ==== combine + state update (tid 512-767) ===========================
        if (tid >= 512 && tid < 768) {
            #pragma unroll
            for (int g = 0; g < GB; g++) {
                float y = bfc_v + wfc_y * s.syh[g][step] + s.spart[2 * g] + s.spart[2 * g + 1];
                float gi = fIF[g].x + b4.x + wi4.x * y;
                float gf = fIF[g].y + b4.y + wi4.y * y;
                float gg = fGO[g].x + b4.z + wi4.z * y;
                float go = fGO[g].y + b4.w + wi4.w * y;
                float cold = s.shc[g][256 + k];
                float cn = sigm(gf) * cold + sigm(gi) * tanh_acc(gg);
                float hn = sigm(go) * tanh_acc(cn);
                s.shc[g][256 + k] = cn;
                s.shc[g][k] = hn;
                __half2 hs = __float2half2_rn(hn);
                s.shD[g][k] = *(unsigned*)&hs;
            }
        }
        __syncthreads();   // end of step
    }
    // ---- final: out[b] = b_fcf + Wfcf . [h ; context] -----------------------
    #pragma unroll
    for (int g = 0; g < GB; g++) {
        float v = (tid < 256)
                    ? (Wfcf[k] * s.shc[g][k] + Wfcf[256 + k] * s.sctx[g][k]) : 0.f;
        #pragma unroll
        for (int o = 16; o; o >>= 1) v += __shfl_down_sync(0xffffffffu, v, o);
        if (lane == 0) s.sred[warp] = v;
        __syncthreads();
        if (warp == 0) {
            float r = s.sred[lane];
            #pragma unroll
            for (int o = 16; o; o >>= 1) r += __shfl_down_sync(0xffffffffu, r, o);
            if (lane == 0) out[bs + g] = bfcf[0] + r;
        }
        __syncthreads();
    }
}

// ---------------- launch -----------------------------------------------------
extern "C" void kernel_launch(void* const* d_in, const int* in_sizes, int n_in,
                              void* d_out, int out_size) {
    const float* enc  = (const float*)d_in[0];
    const float* yh   = (const float*)d_in[1];
    const float* W1   = (const float*)d_in[2];
    const float* b1   = (const float*)d_in[3];
    const float* W2   = (const float*)d_in[4];
    // d_in[5] = b_attn2: softmax-invariant, unused
    const float* Wih  = (const float*)d_in[6];
    const float* Whh  = (const float*)d_in[7];
    const float* bih  = (const float*)d_in[8];
    const float* bhh  = (const float*)d_in[9];
    const float* Wfc  = (const float*)d_in[10];
    const float* bfc  = (const float*)d_in[11];
    const float* Wfcf = (const float*)d_in[12];
    const float* bfcf = (const float*)d_in[13];
    float* out = (float*)d_out;

    static bool attr_done = false;
    if (!attr_done) {
        cudaFuncSetAttribute(decoder_kernel,
                             cudaFuncAttributeMaxDynamicSharedMemorySize, sizeof(SmemT));
        attr_done = true;
    }
    prep_kernel<<<256, 256>>>(W1, Whh, bih, bhh, Wih, enc);
    e_gemm<<<dim3(1016, 4), 256>>>(enc, b1);
    decoder_kernel<<<NCTA, 1024, sizeof(SmemT)>>>(yh, W2, Wfc, bfc, Wfcf, bfcf, out);
}